// round 14
// baseline (speedup 1.0000x reference)
#include <cuda_runtime.h>
#include <math.h>
#include <stdint.h>

#define T_STEPS 512
#define BATCH   256
#define IN_DIM  256
#define HID     512
#define OUT_DIM 128
#define BT      16     // b-tile rows per CTA
#define CT      64     // c-tile cols per CTA
#define CLUSTER 8      // CTAs per b-group (= HID/CT)
#define C_INV   (1.0f / 255.0f)   // XLA rewrite: y/255 -> y * (1/255)

// Scratch (allocation-free rule: __device__ globals)
__device__ float d_XW[(size_t)T_STEPS * BATCH * HID];   // u = x@W_ih^T + b_ih, layout [T*B][H]
__device__ float d_hbuf[2][HID * BATCH];                // h transposed: [c(=H)][b]

__device__ __forceinline__ uint32_t smem_u32(const void* p) {
    uint32_t a;
    asm("{ .reg .u64 t; cvta.to.shared.u64 t, %1; cvt.u32.u64 %0, t; }" : "=r"(a) : "l"(p));
    return a;
}
__device__ __forceinline__ void cp_async16(uint32_t dst, const void* src) {
    asm volatile("cp.async.cg.shared.global [%0], [%1], 16;" :: "r"(dst), "l"(src) : "memory");
}
__device__ __forceinline__ void cp_commit() {
    asm volatile("cp.async.commit_group;" ::: "memory");
}
__device__ __forceinline__ void cp_wait0() {
    asm volatile("cp.async.wait_group 0;" ::: "memory");
}
__device__ __forceinline__ void cluster_sync_() {
    asm volatile("barrier.cluster.arrive.aligned;" ::: "memory");
    asm volatile("barrier.cluster.wait.aligned;" ::: "memory");
}

// ---------------- Kernel A: u = x @ W_ih^T + b_ih ----------------
// fp32 FMA, strictly ascending k, single accumulator (bit-exact). At FFMA roofline.
__global__ __launch_bounds__(256) void gemm_xw(
    const float* __restrict__ X, const float* __restrict__ Wih,
    const float* __restrict__ bih)
{
    __shared__ float As[8][128];
    __shared__ float Bs[8][128];
    const int tid = threadIdx.x;
    const int m0 = blockIdx.y * 128;
    const int n0 = blockIdx.x * 128;
    const int lr = tid >> 1;
    const int lk = (tid & 1) * 4;
    const int tx = tid & 15;
    const int ty = tid >> 4;

    float acc[8][8];
#pragma unroll
    for (int i = 0; i < 8; i++)
#pragma unroll
        for (int j = 0; j < 8; j++) acc[i][j] = 0.0f;

    for (int k0 = 0; k0 < IN_DIM; k0 += 8) {
        float4 va = *(const float4*)&X[(size_t)(m0 + lr) * IN_DIM + k0 + lk];
        float4 vb = *(const float4*)&Wih[(size_t)(n0 + lr) * IN_DIM + k0 + lk];
        __syncthreads();
        As[lk + 0][lr] = va.x; As[lk + 1][lr] = va.y; As[lk + 2][lr] = va.z; As[lk + 3][lr] = va.w;
        Bs[lk + 0][lr] = vb.x; Bs[lk + 1][lr] = vb.y; Bs[lk + 2][lr] = vb.z; Bs[lk + 3][lr] = vb.w;
        __syncthreads();
#pragma unroll
        for (int k = 0; k < 8; k++) {
            float a[8], b[8];
            *(float4*)&a[0] = *(const float4*)&As[k][ty * 8];
            *(float4*)&a[4] = *(const float4*)&As[k][ty * 8 + 4];
            *(float4*)&b[0] = *(const float4*)&Bs[k][tx * 8];
            *(float4*)&b[4] = *(const float4*)&Bs[k][tx * 8 + 4];
#pragma unroll
            for (int i = 0; i < 8; i++)
#pragma unroll
                for (int j = 0; j < 8; j++) acc[i][j] = fmaf(a[i], b[j], acc[i][j]);
        }
    }

    float bv[8];
#pragma unroll
    for (int j = 0; j < 8; j++) bv[j] = __ldg(bih + n0 + tx * 8 + j);
#pragma unroll
    for (int i = 0; i < 8; i++) {
        int m = m0 + ty * 8 + i;
        float4 o0 = make_float4(__fadd_rn(acc[i][0], bv[0]), __fadd_rn(acc[i][1], bv[1]),
                                __fadd_rn(acc[i][2], bv[2]), __fadd_rn(acc[i][3], bv[3]));
        float4 o1 = make_float4(__fadd_rn(acc[i][4], bv[4]), __fadd_rn(acc[i][5], bv[5]),
                                __fadd_rn(acc[i][6], bv[6]), __fadd_rn(acc[i][7], bv[7]));
        *(float4*)&d_XW[(size_t)m * HID + n0 + tx * 8]     = o0;
        *(float4*)&d_XW[(size_t)m * HID + n0 + tx * 8 + 4] = o1;
    }
}

// ---------------- Kernel B: clustered recurrence (fp32 FMA ascending) ----------------
// Grid (8, 16): x = c-tile (cluster dim), y = b-tile. CTA = 16b x 64c, 256 threads.
// Each cluster of 8 CTAs owns one b-tile chain — fully independent of other clusters.
// cluster.sync() is the only cross-CTA barrier (release/acquire at cluster scope).
__global__ __launch_bounds__(256) __cluster_dims__(CLUSTER, 1, 1)
void rnn_steps(const float* __restrict__ Whh, const float* __restrict__ bhh)
{
    extern __shared__ float smem[];
    float* Wsm = smem;                  // [512][64]  Wsm[k*64+c] = Whh[c0+c][k]  (128 KB)
    float* hsm = smem + HID * CT;       // [512][16]  hsm[k*16+b] = h_prev[k][b0+b] (32 KB)

    const int tid = threadIdx.x;
    const int c0 = blockIdx.x * CT;
    const int b0 = blockIdx.y * BT;
    const int b  = tid & 15;            // 0..15
    const int c4 = (tid >> 4) << 2;     // 0,4,...,60

    // Persistent W_hh slice (coalesced global reads along k).
    for (int idx = tid; idx < HID * CT; idx += 256) {
        int c = idx >> 9;               // 0..63
        int k = idx & 511;
        Wsm[k * CT + c] = Whh[(size_t)(c0 + c) * HID + k];
    }

    float bh[4];
#pragma unroll
    for (int j = 0; j < 4; j++) bh[j] = __ldg(bhh + c0 + c4 + j);
    __syncthreads();

    // ---- t = 0: h0 = 0 -> z = (u + 0) + b_hh ----
    {
        float4 uv = __ldg((const float4*)&d_XW[((size_t)(b0 + b)) * HID + c0 + c4]);
        float* hn = d_hbuf[0];
        float z0 = __fadd_rn(__fadd_rn(uv.x, 0.0f), bh[0]);
        float z1 = __fadd_rn(__fadd_rn(uv.y, 0.0f), bh[1]);
        float z2 = __fadd_rn(__fadd_rn(uv.z, 0.0f), bh[2]);
        float z3 = __fadd_rn(__fadd_rn(uv.w, 0.0f), bh[3]);
        z0 = fminf(fmaxf(z0, 0.0f), 255.0f);
        z1 = fminf(fmaxf(z1, 0.0f), 255.0f);
        z2 = fminf(fmaxf(z2, 0.0f), 255.0f);
        z3 = fminf(fmaxf(z3, 0.0f), 255.0f);
        hn[(c0 + c4 + 0) * BATCH + b0 + b] = sqrtf(__fmul_rn(z0, C_INV)) * 255.0f;
        hn[(c0 + c4 + 1) * BATCH + b0 + b] = sqrtf(__fmul_rn(z1, C_INV)) * 255.0f;
        hn[(c0 + c4 + 2) * BATCH + b0 + b] = sqrtf(__fmul_rn(z2, C_INV)) * 255.0f;
        hn[(c0 + c4 + 3) * BATCH + b0 + b] = sqrtf(__fmul_rn(z3, C_INV)) * 255.0f;
    }

    for (int t = 1; t < T_STEPS; t++) {
        // Prefetch u for this step (static data) before the cluster barrier.
        float4 uv = __ldg((const float4*)&d_XW[((size_t)t * BATCH + b0 + b) * HID + c0 + c4]);

        // ---- cluster barrier: h[t-1] stores of all 8 group CTAs visible; also
        //      guarantees peers finished reading h[t-2] buffer we write next. ----
        cluster_sync_();

        // Stage h_prev (512k x 16b = 32 KB) in one burst: 8 cp.async.cg per thread.
        const float* hp = d_hbuf[(t - 1) & 1];
#pragma unroll
        for (int i = 0; i < 8; i++) {
            int idx = tid + i * 256;            // 0..2047 float4 slots
            int k = idx >> 2;                   // 0..511
            int col = (idx & 3) * 4;            // 0,4,8,12
            cp_async16(smem_u32(&hsm[k * BT + col]), &hp[k * BATCH + b0 + col]);
        }
        cp_commit();
        cp_wait0();
        __syncthreads();

        // Uninterrupted ascending-k FMA chain (bit-exact winning semantics).
        float acc0 = 0.0f, acc1 = 0.0f, acc2 = 0.0f, acc3 = 0.0f;
#pragma unroll 8
        for (int k = 0; k < HID; k++) {
            float a = hsm[k * BT + b];                       // 16-bank row + broadcast
            float4 w = *(const float4*)&Wsm[k * CT + c4];    // 2 distinct float4/warp
            acc0 = fmaf(a, w.x, acc0);
            acc1 = fmaf(a, w.y, acc1);
            acc2 = fmaf(a, w.z, acc2);
            acc3 = fmaf(a, w.w, acc3);
        }

        // Epilogue: z = (u + hw) + b_hh; clip; sqrt(z*(1/255))*255.
        float* hn = d_hbuf[t & 1];
        float z0 = __fadd_rn(__fadd_rn(uv.x, acc0), bh[0]);
        float z1 = __fadd_rn(__fadd_rn(uv.y, acc1), bh[1]);
        float z2 = __fadd_rn(__fadd_rn(uv.z, acc2), bh[2]);
        float z3 = __fadd_rn(__fadd_rn(uv.w, acc3), bh[3]);
        z0 = fminf(fmaxf(z0, 0.0f), 255.0f);
        z1 = fminf(fmaxf(z1, 0.0f), 255.0f);
        z2 = fminf(fmaxf(z2, 0.0f), 255.0f);
        z3 = fminf(fmaxf(z3, 0.0f), 255.0f);
        hn[(c0 + c4 + 0) * BATCH + b0 + b] = sqrtf(__fmul_rn(z0, C_INV)) * 255.0f;
        hn[(c0 + c4 + 1) * BATCH + b0 + b] = sqrtf(__fmul_rn(z1, C_INV)) * 255.0f;
        hn[(c0 + c4 + 2) * BATCH + b0 + b] = sqrtf(__fmul_rn(z2, C_INV)) * 255.0f;
        hn[(c0 + c4 + 3) * BATCH + b0 + b] = sqrtf(__fmul_rn(z3, C_INV)) * 255.0f;
    }
}

// ---------------- Kernel C: out = hT @ W_out^T + b_out (fp32 ascending) ----------------
__global__ __launch_bounds__(256) void out_gemm(const float* __restrict__ Wout,
                                                const float* __restrict__ bout,
                                                float* __restrict__ out)
{
    __shared__ float ws[HID];
    const int o = blockIdx.x;
    const int b = threadIdx.x;
    for (int k = threadIdx.x; k < HID; k += 256) ws[k] = Wout[(size_t)o * HID + k];
    __syncthreads();
    const float* h = d_hbuf[(T_STEPS - 1) & 1];
    float acc = 0.0f;
#pragma unroll 8
    for (int k = 0; k < HID; k++) acc = fmaf(h[k * BATCH + b], ws[k], acc);
    out[b * OUT_DIM + o] = __fadd_rn(acc, __ldg(bout + o));
}

extern "C" void kernel_launch(void* const* d_in, const int* in_sizes, int n_in,
                              void* d_out, int out_size)
{
    const float *x = 0, *Wih = 0, *bih = 0, *Whh = 0, *bhh = 0, *Wout = 0, *bout = 0;
    int nb512 = 0;
    for (int i = 0; i < n_in; i++) {
        const float* p = (const float*)d_in[i];
        switch (in_sizes[i]) {
            case 33554432: x = p; break;
            case 262144:   Whh = p; break;
            case 131072:   Wih = p; break;
            case 65536:    Wout = p; break;
            case 128:      bout = p; break;
            case 512:      if (nb512++ == 0) bih = p; else bhh = p; break;
            default: break;
        }
    }
    float* out = (float*)d_out;

    const int rsmem = (HID * CT + HID * BT) * (int)sizeof(float);   // 163840 B
    cudaFuncSetAttribute(rnn_steps, cudaFuncAttributeMaxDynamicSharedMemorySize, rsmem);

    dim3 gA(HID / 128, (T_STEPS * BATCH) / 128);                    // (4, 1024)
    gemm_xw<<<gA, 256>>>(x, Wih, bih);
    rnn_steps<<<dim3(HID / CT, BATCH / BT), 256, rsmem>>>(Whh, bhh); // (8, 16), clusters of 8
    out_gemm<<<OUT_DIM, 256>>>(Wout, bout, out);
}

// round 15
// speedup vs baseline: 1.7202x; 1.7202x over previous
#include <cuda_runtime.h>
#include <math.h>
#include <stdint.h>

#define T_STEPS 512
#define BATCH   256
#define IN_DIM  256
#define HID     512
#define OUT_DIM 128
#define NBG     16      // b-groups (16 batch rows each)
#define NCT     16      // c-tiles per group (32 cols each)
#define BT      16      // b rows per CTA
#define CT      32      // c cols per CTA
#define RTH     128     // threads per recurrence CTA
#define C_INV   (1.0f / 255.0f)   // XLA rewrite: y/255 -> y * (1/255)

// Scratch (allocation-free rule: __device__ globals)
__device__ float d_XW[(size_t)T_STEPS * BATCH * HID];   // u = x@W_ih^T + b_ih, [T*B][H]
__device__ float d_hbuf[2][HID * BATCH];                // h transposed: [c(=H)][b]
__device__ unsigned g_flag[NBG * NCT * 32];             // one 128B line per CTA

__device__ __forceinline__ uint32_t smem_u32(const void* p) {
    uint32_t a;
    asm("{ .reg .u64 t; cvta.to.shared.u64 t, %1; cvt.u32.u64 %0, t; }" : "=r"(a) : "l"(p));
    return a;
}
__device__ __forceinline__ void cp_async16(uint32_t dst, const void* src) {
    asm volatile("cp.async.cg.shared.global [%0], [%1], 16;" :: "r"(dst), "l"(src) : "memory");
}
__device__ __forceinline__ void cp_commit() {
    asm volatile("cp.async.commit_group;" ::: "memory");
}
__device__ __forceinline__ void cp_wait0() {
    asm volatile("cp.async.wait_group 0;" ::: "memory");
}

// ---------------- Kernel A: u = x @ W_ih^T + b_ih (unchanged, 892us, near rt2 ceiling) ----
__global__ __launch_bounds__(256) void gemm_xw(
    const float* __restrict__ X, const float* __restrict__ Wih,
    const float* __restrict__ bih)
{
    __shared__ float As[8][128];
    __shared__ float Bs[8][128];
    const int tid = threadIdx.x;
    const int m0 = blockIdx.y * 128;
    const int n0 = blockIdx.x * 128;
    const int lr = tid >> 1;
    const int lk = (tid & 1) * 4;
    const int tx = tid & 15;
    const int ty = tid >> 4;

    float acc[8][8];
#pragma unroll
    for (int i = 0; i < 8; i++)
#pragma unroll
        for (int j = 0; j < 8; j++) acc[i][j] = 0.0f;

    for (int k0 = 0; k0 < IN_DIM; k0 += 8) {
        float4 va = *(const float4*)&X[(size_t)(m0 + lr) * IN_DIM + k0 + lk];
        float4 vb = *(const float4*)&Wih[(size_t)(n0 + lr) * IN_DIM + k0 + lk];
        __syncthreads();
        As[lk + 0][lr] = va.x; As[lk + 1][lr] = va.y; As[lk + 2][lr] = va.z; As[lk + 3][lr] = va.w;
        Bs[lk + 0][lr] = vb.x; Bs[lk + 1][lr] = vb.y; Bs[lk + 2][lr] = vb.z; Bs[lk + 3][lr] = vb.w;
        __syncthreads();
#pragma unroll
        for (int k = 0; k < 8; k++) {
            float a[8], b[8];
            *(float4*)&a[0] = *(const float4*)&As[k][ty * 8];
            *(float4*)&a[4] = *(const float4*)&As[k][ty * 8 + 4];
            *(float4*)&b[0] = *(const float4*)&Bs[k][tx * 8];
            *(float4*)&b[4] = *(const float4*)&Bs[k][tx * 8 + 4];
#pragma unroll
            for (int i = 0; i < 8; i++)
#pragma unroll
                for (int j = 0; j < 8; j++) acc[i][j] = fmaf(a[i], b[j], acc[i][j]);
        }
    }

    float bv[8];
#pragma unroll
    for (int j = 0; j < 8; j++) bv[j] = __ldg(bih + n0 + tx * 8 + j);
#pragma unroll
    for (int i = 0; i < 8; i++) {
        int m = m0 + ty * 8 + i;
        float4 o0 = make_float4(__fadd_rn(acc[i][0], bv[0]), __fadd_rn(acc[i][1], bv[1]),
                                __fadd_rn(acc[i][2], bv[2]), __fadd_rn(acc[i][3], bv[3]));
        float4 o1 = make_float4(__fadd_rn(acc[i][4], bv[4]), __fadd_rn(acc[i][5], bv[5]),
                                __fadd_rn(acc[i][6], bv[6]), __fadd_rn(acc[i][7], bv[7]));
        *(float4*)&d_XW[(size_t)m * HID + n0 + tx * 8]     = o0;
        *(float4*)&d_XW[(size_t)m * HID + n0 + tx * 8 + 4] = o1;
    }
}

// ---------------- Kernel B: recurrence, 256 CTAs (16 b-groups x 16 c-tiles) ----------------
// CTA = 16b x 32c, 128 threads, 96 KB smem -> 2 CTAs/SM (independent chains overlap).
// Group-local flag barrier: each CTA polls only its b-group's 16 flags (gpu-scope acq/rel).
__global__ __launch_bounds__(RTH) void rnn_steps(
    const float* __restrict__ Whh, const float* __restrict__ bhh)
{
    extern __shared__ float smem[];
    float* Wsm = smem;                  // [512][32]  Wsm[k*32+c] = Whh[c0+c][k]   (64 KB)
    float* hsm = smem + HID * CT;       // [512][16]  hsm[k*16+b] = h_prev[k][b0+b] (32 KB)

    const int tid = threadIdx.x;
    const int bx = blockIdx.x;          // c-tile 0..15
    const int by = blockIdx.y;          // b-group 0..15
    const int c0 = bx * CT;
    const int b0 = by * BT;
    const int b  = tid & 15;            // 0..15
    const int c4 = (tid >> 4) << 2;     // 0,4,...,28
    unsigned* myflag = &g_flag[(by * NCT + bx) * 32];

    // Replay-safe barrier base (all flags equal at kernel entry).
    const unsigned base = *(volatile unsigned*)myflag;

    // Persistent W_hh slice (coalesced along k).
    for (int idx = tid; idx < HID * CT; idx += RTH) {
        int c = idx >> 9;               // 0..31
        int k = idx & 511;
        Wsm[k * CT + c] = Whh[(size_t)(c0 + c) * HID + k];
    }

    float bh[4];
#pragma unroll
    for (int j = 0; j < 4; j++) bh[j] = __ldg(bhh + c0 + c4 + j);
    __syncthreads();

    // ---- t = 0: h0 = 0 -> z = (u + 0) + b_hh (skip GEMM) ----
    {
        float4 uv = __ldg((const float4*)&d_XW[((size_t)(b0 + b)) * HID + c0 + c4]);
        float* hn = d_hbuf[0];
        float z0 = __fadd_rn(__fadd_rn(uv.x, 0.0f), bh[0]);
        float z1 = __fadd_rn(__fadd_rn(uv.y, 0.0f), bh[1]);
        float z2 = __fadd_rn(__fadd_rn(uv.z, 0.0f), bh[2]);
        float z3 = __fadd_rn(__fadd_rn(uv.w, 0.0f), bh[3]);
        z0 = fminf(fmaxf(z0, 0.0f), 255.0f);
        z1 = fminf(fmaxf(z1, 0.0f), 255.0f);
        z2 = fminf(fmaxf(z2, 0.0f), 255.0f);
        z3 = fminf(fmaxf(z3, 0.0f), 255.0f);
        hn[(c0 + c4 + 0) * BATCH + b0 + b] = sqrtf(__fmul_rn(z0, C_INV)) * 255.0f;
        hn[(c0 + c4 + 1) * BATCH + b0 + b] = sqrtf(__fmul_rn(z1, C_INV)) * 255.0f;
        hn[(c0 + c4 + 2) * BATCH + b0 + b] = sqrtf(__fmul_rn(z2, C_INV)) * 255.0f;
        hn[(c0 + c4 + 3) * BATCH + b0 + b] = sqrtf(__fmul_rn(z3, C_INV)) * 255.0f;
    }

    for (int t = 1; t < T_STEPS; t++) {
        // Prefetch u for this step before the barrier (hides DRAM latency).
        float4 uv = __ldg((const float4*)&d_XW[((size_t)t * BATCH + b0 + b) * HID + c0 + c4]);

        // ---- group barrier (16 CTAs sharing this b-group), CG release/acquire ----
        __syncthreads();
        if (tid == 0)
            asm volatile("st.release.gpu.u32 [%0], %1;"
                         :: "l"(myflag), "r"(base + (unsigned)t) : "memory");
        if (tid < NCT) {
            const unsigned tgt = base + (unsigned)t;
            unsigned v;
            do {
                asm volatile("ld.acquire.gpu.u32 %0, [%1];"
                             : "=r"(v) : "l"(&g_flag[(by * NCT + tid) * 32]) : "memory");
            } while (v < tgt);
        }
        __syncthreads();

        const float* hp = d_hbuf[(t - 1) & 1];

        // Stage chunk 0 (k in [0,128)): 512 float4 slots, 4/thread, cp.async.cg (L2-only).
#pragma unroll
        for (int i = 0; i < 4; i++) {
            int idx = tid + i * RTH;            // 0..511
            int k = idx >> 2;                   // 0..127
            int col = (idx & 3) * 4;            // 0,4,8,12
            cp_async16(smem_u32(&hsm[k * BT + col]), &hp[k * BATCH + b0 + col]);
        }
        cp_commit();
        cp_wait0();
        __syncthreads();

        float acc0 = 0.0f, acc1 = 0.0f, acc2 = 0.0f, acc3 = 0.0f;
#pragma unroll
        for (int ch = 0; ch < 4; ch++) {
            if (ch < 3) {                       // stage next chunk during compute
#pragma unroll
                for (int i = 0; i < 4; i++) {
                    int idx = tid + i * RTH;
                    int k = (ch + 1) * 128 + (idx >> 2);
                    int col = (idx & 3) * 4;
                    cp_async16(smem_u32(&hsm[k * BT + col]), &hp[k * BATCH + b0 + col]);
                }
                cp_commit();
            }
            const int kend = ch * 128 + 128;
#pragma unroll 8
            for (int k = ch * 128; k < kend; k++) {   // strictly ascending k overall
                float a = hsm[k * BT + b];                       // conflict-free + broadcast
                float4 w = *(const float4*)&Wsm[k * CT + c4];    // 2 distinct float4/warp
                acc0 = fmaf(a, w.x, acc0);
                acc1 = fmaf(a, w.y, acc1);
                acc2 = fmaf(a, w.z, acc2);
                acc3 = fmaf(a, w.w, acc3);
            }
            if (ch < 3) {
                cp_wait0();
                __syncthreads();
            }
        }

        // Epilogue: z = (u + hw) + b_hh; clip; sqrt(z*(1/255))*255.
        float* hn = d_hbuf[t & 1];
        float z0 = __fadd_rn(__fadd_rn(uv.x, acc0), bh[0]);
        float z1 = __fadd_rn(__fadd_rn(uv.y, acc1), bh[1]);
        float z2 = __fadd_rn(__fadd_rn(uv.z, acc2), bh[2]);
        float z3 = __fadd_rn(__fadd_rn(uv.w, acc3), bh[3]);
        z0 = fminf(fmaxf(z0, 0.0f), 255.0f);
        z1 = fminf(fmaxf(z1, 0.0f), 255.0f);
        z2 = fminf(fmaxf(z2, 0.0f), 255.0f);
        z3 = fminf(fmaxf(z3, 0.0f), 255.0f);
        hn[(c0 + c4 + 0) * BATCH + b0 + b] = sqrtf(__fmul_rn(z0, C_INV)) * 255.0f;
        hn[(c0 + c4 + 1) * BATCH + b0 + b] = sqrtf(__fmul_rn(z1, C_INV)) * 255.0f;
        hn[(c0 + c4 + 2) * BATCH + b0 + b] = sqrtf(__fmul_rn(z2, C_INV)) * 255.0f;
        hn[(c0 + c4 + 3) * BATCH + b0 + b] = sqrtf(__fmul_rn(z3, C_INV)) * 255.0f;
    }
}

// ---------------- Kernel C: out = hT @ W_out^T + b_out (fp32 ascending) ----------------
__global__ __launch_bounds__(256) void out_gemm(const float* __restrict__ Wout,
                                                const float* __restrict__ bout,
                                                float* __restrict__ out)
{
    __shared__ float ws[HID];
    const int o = blockIdx.x;
    const int b = threadIdx.x;
    for (int k = threadIdx.x; k < HID; k += 256) ws[k] = Wout[(size_t)o * HID + k];
    __syncthreads();
    const float* h = d_hbuf[(T_STEPS - 1) & 1];
    float acc = 0.0f;
#pragma unroll 8
    for (int k = 0; k < HID; k++) acc = fmaf(h[k * BATCH + b], ws[k], acc);
    out[b * OUT_DIM + o] = __fadd_rn(acc, __ldg(bout + o));
}

extern "C" void kernel_launch(void* const* d_in, const int* in_sizes, int n_in,
                              void* d_out, int out_size)
{
    const float *x = 0, *Wih = 0, *bih = 0, *Whh = 0, *bhh = 0, *Wout = 0, *bout = 0;
    int nb512 = 0;
    for (int i = 0; i < n_in; i++) {
        const float* p = (const float*)d_in[i];
        switch (in_sizes[i]) {
            case 33554432: x = p; break;
            case 262144:   Whh = p; break;
            case 131072:   Wih = p; break;
            case 65536:    Wout = p; break;
            case 128:      bout = p; break;
            case 512:      if (nb512++ == 0) bih = p; else bhh = p; break;
            default: break;
        }
    }
    float* out = (float*)d_out;

    const int rsmem = (HID * CT + HID * BT) * (int)sizeof(float);   // 98304 B -> 2 CTAs/SM
    cudaFuncSetAttribute(rnn_steps, cudaFuncAttributeMaxDynamicSharedMemorySize, rsmem);

    dim3 gA(HID / 128, (T_STEPS * BATCH) / 128);                    // (4, 1024)
    gemm_xw<<<gA, 256>>>(x, Wih, bih);
    rnn_steps<<<dim3(NCT, NBG), RTH, rsmem>>>(Whh, bhh);            // 256 CTAs, 296 slots
    out_gemm<<<OUT_DIM, 256>>>(Wout, bout, out);
}